// round 2
// baseline (speedup 1.0000x reference)
#include <cuda_runtime.h>
#include <cuda_bf16.h>
#include <cstdint>

#define NN 8192
#define DD 128
#define TAU 0.1f

static __device__ __nv_bfloat16 g_t[NN * DD];   // t = MLP(Z), bf16
static __device__ __nv_bfloat16 g_zb[NN * DD];  // Z in bf16 (V operand)

__device__ __forceinline__ uint32_t packbf(float a, float b) {
    __nv_bfloat162 h = __floats2bfloat162_rn(a, b);
    return *reinterpret_cast<uint32_t*>(&h);
}

__device__ __forceinline__ void mma16816(float c[4], const uint32_t a[4],
                                         uint32_t b0, uint32_t b1) {
    asm volatile(
        "mma.sync.aligned.m16n8k16.row.col.f32.bf16.bf16.f32 "
        "{%0,%1,%2,%3}, {%4,%5,%6,%7}, {%8,%9}, {%0,%1,%2,%3};\n"
        : "+f"(c[0]), "+f"(c[1]), "+f"(c[2]), "+f"(c[3])
        : "r"(a[0]), "r"(a[1]), "r"(a[2]), "r"(a[3]), "r"(b0), "r"(b1));
}

// ---------------------------------------------------------------------------
// MLP: t = relu(Z@W1 + b1) @ W2 + b2, written as bf16. Also emits Zb = bf16(Z).
// Grid 128 blocks x 256 threads; 64 rows per block. W tiles staged in smem
// transposed so each thread reads its column with float4 LDS.
// ---------------------------------------------------------------------------
__global__ __launch_bounds__(256) void mlp_kernel(
    const float* __restrict__ Z, const float* __restrict__ W1,
    const float* __restrict__ b1, const float* __restrict__ W2,
    const float* __restrict__ b2)
{
    __shared__ float wsT[128][36];            // [out j][k-tile 32] padded
    __shared__ float zs[64][36];              // [row][k-tile 32] padded
    __shared__ __nv_bfloat16 hs[64][128];     // hidden activations

    const int tid = threadIdx.x;
    const int j = tid & 127;                  // output column
    const int rh = tid >> 7;                  // row-half (0/1)
    const int rb = blockIdx.x * 64;

    float acc[32];
#pragma unroll
    for (int r = 0; r < 32; r++) acc[r] = 0.f;

    // ---- phase 1: h = relu(Z @ W1 + b1) ----
    for (int kt = 0; kt < 4; kt++) {
        for (int i = tid; i < 4096; i += 256) {
            int kk = i >> 7, jj = i & 127;
            wsT[jj][kk] = W1[(kt * 32 + kk) * 128 + jj];
        }
        for (int i = tid; i < 2048; i += 256) {
            int r = i >> 5, kk = i & 31;
            zs[r][kk] = Z[(rb + r) * 128 + kt * 32 + kk];
        }
        __syncthreads();
#pragma unroll
        for (int kk4 = 0; kk4 < 8; kk4++) {
            float4 w = *(const float4*)&wsT[j][kk4 * 4];
#pragma unroll
            for (int r = 0; r < 32; r++) {
                float4 z = *(const float4*)&zs[rh * 32 + r][kk4 * 4];
                acc[r] += z.x * w.x + z.y * w.y + z.z * w.z + z.w * w.w;
            }
        }
        __syncthreads();
    }
    {
        float bb = b1[j];
#pragma unroll
        for (int r = 0; r < 32; r++) {
            float h = acc[r] + bb;
            hs[rh * 32 + r][j] = __float2bfloat16(h > 0.f ? h : 0.f);
            acc[r] = 0.f;
        }
    }
    __syncthreads();

    // ---- phase 2: t = h @ W2 + b2 ----
    for (int kt = 0; kt < 4; kt++) {
        for (int i = tid; i < 4096; i += 256) {
            int kk = i >> 7, jj = i & 127;
            wsT[jj][kk] = W2[(kt * 32 + kk) * 128 + jj];
        }
        __syncthreads();
#pragma unroll
        for (int kk4 = 0; kk4 < 8; kk4++) {
            float4 w = *(const float4*)&wsT[j][kk4 * 4];
#pragma unroll
            for (int r = 0; r < 32; r++) {
                const uint32_t* hp =
                    (const uint32_t*)&hs[rh * 32 + r][kt * 32 + kk4 * 4];
                __nv_bfloat162 h01 = *(const __nv_bfloat162*)&hp[0];
                __nv_bfloat162 h23 = *(const __nv_bfloat162*)&hp[1];
                acc[r] += __bfloat162float(h01.x) * w.x +
                          __bfloat162float(h01.y) * w.y +
                          __bfloat162float(h23.x) * w.z +
                          __bfloat162float(h23.y) * w.w;
            }
        }
        __syncthreads();
    }
    {
        float bb = b2[j];
#pragma unroll
        for (int r = 0; r < 32; r++) {
            int row = rb + rh * 32 + r;
            g_t[row * 128 + j] = __float2bfloat16(acc[r] + bb);
        }
    }
    for (int i = tid; i < 64 * 128; i += 256) {
        g_zb[rb * 128 + i] = __float2bfloat16(Z[rb * 128 + i]);
    }
}

// ---------------------------------------------------------------------------
// Fused flash-attention-style kernel:
//   out = Z + TAU * (softmax(t t^T) @ Z - Z)
// Q=K=t (bf16), V=Zb (bf16). BM=64 rows per CTA, BN=64 keys per step,
// online softmax entirely in registers (mma C-frag layout == A-frag layout).
// ---------------------------------------------------------------------------
__global__ __launch_bounds__(128, 1) void flash_kernel(
    const float* __restrict__ Z, float* __restrict__ out)
{
    __shared__ __nv_bfloat16 sK[64][136];   // K tile (also Q staging), row-major
    __shared__ __nv_bfloat16 sVt[128][72];  // V tile TRANSPOSED: [d][key]

    const int tid = threadIdx.x;
    const int lane = tid & 31;
    const int warp = tid >> 5;
    const int g = lane >> 2;    // mma group id (row within 8)
    const int t4 = lane & 3;    // mma thread-in-group (col pair)
    const int rb = blockIdx.x * 64;

    // stage Q tile, pull A-fragments into registers (held for whole kernel)
    for (int i = tid; i < 1024; i += 128) {
        int r = i >> 4, c = i & 15;
        *(uint4*)&sK[r][c * 8] = *(const uint4*)&g_t[(rb + r) * 128 + c * 8];
    }
    __syncthreads();
    uint32_t qf[8][4];
    const int qr = warp * 16 + g;
#pragma unroll
    for (int kc = 0; kc < 8; kc++) {
        qf[kc][0] = *(const uint32_t*)&sK[qr][kc * 16 + 2 * t4];
        qf[kc][1] = *(const uint32_t*)&sK[qr + 8][kc * 16 + 2 * t4];
        qf[kc][2] = *(const uint32_t*)&sK[qr][kc * 16 + 8 + 2 * t4];
        qf[kc][3] = *(const uint32_t*)&sK[qr + 8][kc * 16 + 8 + 2 * t4];
    }
    __syncthreads();

    float o[16][4];
#pragma unroll
    for (int dn = 0; dn < 16; dn++) {
        o[dn][0] = 0.f; o[dn][1] = 0.f; o[dn][2] = 0.f; o[dn][3] = 0.f;
    }
    float m0 = -1e30f, m1 = -1e30f, l0 = 0.f, l1 = 0.f;

    for (int kt = 0; kt < NN / 64; kt++) {
        const int kb = kt * 64;
        // load K tile (row-major) and V tile (transposed)
        for (int i = tid; i < 1024; i += 128) {
            int r = i >> 4, c = i & 15;
            *(uint4*)&sK[r][c * 8] = *(const uint4*)&g_t[(kb + r) * 128 + c * 8];
        }
        for (int i = tid; i < 1024; i += 128) {
            int r = i >> 4, c = i & 15;
            uint4 v = *(const uint4*)&g_zb[(kb + r) * 128 + c * 8];
            const __nv_bfloat16* pv = (const __nv_bfloat16*)&v;
#pragma unroll
            for (int e = 0; e < 8; e++) sVt[c * 8 + e][r] = pv[e];
        }
        __syncthreads();

        // S = Q K^T  (16x64 per warp, fp32 accum)
        float sc[8][4];
#pragma unroll
        for (int nc = 0; nc < 8; nc++) {
            sc[nc][0] = 0.f; sc[nc][1] = 0.f; sc[nc][2] = 0.f; sc[nc][3] = 0.f;
#pragma unroll
            for (int kc = 0; kc < 8; kc++) {
                uint32_t b0 = *(const uint32_t*)&sK[nc * 8 + g][kc * 16 + 2 * t4];
                uint32_t b1 = *(const uint32_t*)&sK[nc * 8 + g][kc * 16 + 8 + 2 * t4];
                mma16816(sc[nc], qf[kc], b0, b1);
            }
        }

        // online softmax
        float mt0 = -1e30f, mt1 = -1e30f;
#pragma unroll
        for (int nc = 0; nc < 8; nc++) {
            mt0 = fmaxf(mt0, fmaxf(sc[nc][0], sc[nc][1]));
            mt1 = fmaxf(mt1, fmaxf(sc[nc][2], sc[nc][3]));
        }
        mt0 = fmaxf(mt0, __shfl_xor_sync(0xffffffffu, mt0, 1));
        mt0 = fmaxf(mt0, __shfl_xor_sync(0xffffffffu, mt0, 2));
        mt1 = fmaxf(mt1, __shfl_xor_sync(0xffffffffu, mt1, 1));
        mt1 = fmaxf(mt1, __shfl_xor_sync(0xffffffffu, mt1, 2));
        float mn0 = fmaxf(m0, mt0), mn1 = fmaxf(m1, mt1);
        float cs0 = __expf(m0 - mn0), cs1 = __expf(m1 - mn1);

        uint32_t pf[4][4];
        float s0 = 0.f, s1 = 0.f;
#pragma unroll
        for (int nc = 0; nc < 8; nc++) {
            float e0 = __expf(sc[nc][0] - mn0);
            float e1 = __expf(sc[nc][1] - mn0);
            float e2 = __expf(sc[nc][2] - mn1);
            float e3 = __expf(sc[nc][3] - mn1);
            s0 += e0 + e1; s1 += e2 + e3;
            if (nc & 1) { pf[nc >> 1][2] = packbf(e0, e1); pf[nc >> 1][3] = packbf(e2, e3); }
            else        { pf[nc >> 1][0] = packbf(e0, e1); pf[nc >> 1][1] = packbf(e2, e3); }
        }
        s0 += __shfl_xor_sync(0xffffffffu, s0, 1);
        s0 += __shfl_xor_sync(0xffffffffu, s0, 2);
        s1 += __shfl_xor_sync(0xffffffffu, s1, 1);
        s1 += __shfl_xor_sync(0xffffffffu, s1, 2);
        l0 = l0 * cs0 + s0;
        l1 = l1 * cs1 + s1;

#pragma unroll
        for (int dn = 0; dn < 16; dn++) {
            o[dn][0] *= cs0; o[dn][1] *= cs0; o[dn][2] *= cs1; o[dn][3] *= cs1;
        }
        // O += P @ V  (B-fragments are contiguous 32-bit words of sVt rows)
#pragma unroll
        for (int dn = 0; dn < 16; dn++) {
#pragma unroll
            for (int kc2 = 0; kc2 < 4; kc2++) {
                uint32_t b0 = *(const uint32_t*)&sVt[dn * 8 + g][kc2 * 16 + 2 * t4];
                uint32_t b1 = *(const uint32_t*)&sVt[dn * 8 + g][kc2 * 16 + 8 + 2 * t4];
                mma16816(o[dn], pf[kc2], b0, b1);
            }
        }
        m0 = mn0; m1 = mn1;
        __syncthreads();
    }

    // epilogue: out = Z + TAU * (O/l - Z), fp32 residual from original Z
    const float i0 = 1.f / l0, i1 = 1.f / l1;
    const int r0 = rb + warp * 16 + g, r1 = r0 + 8;
#pragma unroll
    for (int dn = 0; dn < 16; dn++) {
        int c = dn * 8 + 2 * t4;
        float z00 = Z[r0 * 128 + c], z01 = Z[r0 * 128 + c + 1];
        float z10 = Z[r1 * 128 + c], z11 = Z[r1 * 128 + c + 1];
        out[r0 * 128 + c]     = z00 + TAU * (o[dn][0] * i0 - z00);
        out[r0 * 128 + c + 1] = z01 + TAU * (o[dn][1] * i0 - z01);
        out[r1 * 128 + c]     = z10 + TAU * (o[dn][2] * i1 - z10);
        out[r1 * 128 + c + 1] = z11 + TAU * (o[dn][3] * i1 - z11);
    }
}

extern "C" void kernel_launch(void* const* d_in, const int* in_sizes, int n_in,
                              void* d_out, int out_size)
{
    (void)in_sizes; (void)n_in; (void)out_size;
    const float* Z  = (const float*)d_in[0];
    const float* W1 = (const float*)d_in[1];
    const float* b1 = (const float*)d_in[2];
    const float* W2 = (const float*)d_in[3];
    const float* b2 = (const float*)d_in[4];
    float* out = (float*)d_out;

    mlp_kernel<<<128, 256>>>(Z, W1, b1, W2, b2);
    flash_kernel<<<128, 128>>>(Z, out);
}

// round 3
// speedup vs baseline: 2.8071x; 2.8071x over previous
#include <cuda_runtime.h>
#include <cuda_bf16.h>
#include <cstdint>

#define NN 8192
#define DD 128
#define TAU 0.1f
#define RSH 136                  // smem row stride in halves (128 data + 8 pad)
#define RSB 272                  // row stride in bytes
#define TILE_B 17408             // one K-or-V tile: 64*136*2 bytes
#define BUF_B 34816              // K+V tile pair
#define SMEM_TOTAL 69632         // 2 buffers

static __device__ __nv_bfloat16 g_t[NN * DD];   // t = MLP(Z), bf16
static __device__ __nv_bfloat16 g_zb[NN * DD];  // Z in bf16 (V operand)

__device__ __forceinline__ uint32_t packbf(float a, float b) {
    __nv_bfloat162 h = __floats2bfloat162_rn(a, b);
    return *reinterpret_cast<uint32_t*>(&h);
}

__device__ __forceinline__ uint32_t smem_u32(const void* p) {
    return (uint32_t)__cvta_generic_to_shared(p);
}

__device__ __forceinline__ void mma16816(float c[4], const uint32_t a[4],
                                         uint32_t b0, uint32_t b1) {
    asm volatile(
        "mma.sync.aligned.m16n8k16.row.col.f32.bf16.bf16.f32 "
        "{%0,%1,%2,%3}, {%4,%5,%6,%7}, {%8,%9}, {%0,%1,%2,%3};\n"
        : "+f"(c[0]), "+f"(c[1]), "+f"(c[2]), "+f"(c[3])
        : "r"(a[0]), "r"(a[1]), "r"(a[2]), "r"(a[3]), "r"(b0), "r"(b1));
}

__device__ __forceinline__ void ldm_x4(uint32_t& r0, uint32_t& r1,
                                       uint32_t& r2, uint32_t& r3, uint32_t a) {
    asm volatile("ldmatrix.sync.aligned.m8n8.x4.shared.b16 {%0,%1,%2,%3}, [%4];\n"
                 : "=r"(r0), "=r"(r1), "=r"(r2), "=r"(r3) : "r"(a));
}
__device__ __forceinline__ void ldm_x4_t(uint32_t& r0, uint32_t& r1,
                                         uint32_t& r2, uint32_t& r3, uint32_t a) {
    asm volatile("ldmatrix.sync.aligned.m8n8.x4.trans.shared.b16 {%0,%1,%2,%3}, [%4];\n"
                 : "=r"(r0), "=r"(r1), "=r"(r2), "=r"(r3) : "r"(a));
}

__device__ __forceinline__ void cp_async16(uint32_t s, const void* g) {
    asm volatile("cp.async.cg.shared.global [%0], [%1], 16;\n" :: "r"(s), "l"(g));
}
__device__ __forceinline__ void cp_commit() {
    asm volatile("cp.async.commit_group;\n");
}
template <int N> __device__ __forceinline__ void cp_wait() {
    asm volatile("cp.async.wait_group %0;\n" :: "n"(N));
}

// ---------------------------------------------------------------------------
// MLP: t = relu(Z@W1 + b1) @ W2 + b2 -> bf16; also Zb = bf16(Z). (unchanged)
// ---------------------------------------------------------------------------
__global__ __launch_bounds__(256) void mlp_kernel(
    const float* __restrict__ Z, const float* __restrict__ W1,
    const float* __restrict__ b1, const float* __restrict__ W2,
    const float* __restrict__ b2)
{
    __shared__ float wsT[128][36];
    __shared__ float zs[64][36];
    __shared__ __nv_bfloat16 hs[64][128];

    const int tid = threadIdx.x;
    const int j = tid & 127;
    const int rh = tid >> 7;
    const int rb = blockIdx.x * 64;

    float acc[32];
#pragma unroll
    for (int r = 0; r < 32; r++) acc[r] = 0.f;

    for (int kt = 0; kt < 4; kt++) {
        for (int i = tid; i < 4096; i += 256) {
            int kk = i >> 7, jj = i & 127;
            wsT[jj][kk] = W1[(kt * 32 + kk) * 128 + jj];
        }
        for (int i = tid; i < 2048; i += 256) {
            int r = i >> 5, kk = i & 31;
            zs[r][kk] = Z[(rb + r) * 128 + kt * 32 + kk];
        }
        __syncthreads();
#pragma unroll
        for (int kk4 = 0; kk4 < 8; kk4++) {
            float4 w = *(const float4*)&wsT[j][kk4 * 4];
#pragma unroll
            for (int r = 0; r < 32; r++) {
                float4 z = *(const float4*)&zs[rh * 32 + r][kk4 * 4];
                acc[r] += z.x * w.x + z.y * w.y + z.z * w.z + z.w * w.w;
            }
        }
        __syncthreads();
    }
    {
        float bb = b1[j];
#pragma unroll
        for (int r = 0; r < 32; r++) {
            float h = acc[r] + bb;
            hs[rh * 32 + r][j] = __float2bfloat16(h > 0.f ? h : 0.f);
            acc[r] = 0.f;
        }
    }
    __syncthreads();

    for (int kt = 0; kt < 4; kt++) {
        for (int i = tid; i < 4096; i += 256) {
            int kk = i >> 7, jj = i & 127;
            wsT[jj][kk] = W2[(kt * 32 + kk) * 128 + jj];
        }
        __syncthreads();
#pragma unroll
        for (int kk4 = 0; kk4 < 8; kk4++) {
            float4 w = *(const float4*)&wsT[j][kk4 * 4];
#pragma unroll
            for (int r = 0; r < 32; r++) {
                const uint32_t* hp =
                    (const uint32_t*)&hs[rh * 32 + r][kt * 32 + kk4 * 4];
                __nv_bfloat162 h01 = *(const __nv_bfloat162*)&hp[0];
                __nv_bfloat162 h23 = *(const __nv_bfloat162*)&hp[1];
                acc[r] += __bfloat162float(h01.x) * w.x +
                          __bfloat162float(h01.y) * w.y +
                          __bfloat162float(h23.x) * w.z +
                          __bfloat162float(h23.y) * w.w;
            }
        }
        __syncthreads();
    }
    {
        float bb = b2[j];
#pragma unroll
        for (int r = 0; r < 32; r++) {
            int row = rb + rh * 32 + r;
            g_t[row * 128 + j] = __float2bfloat16(acc[r] + bb);
        }
    }
    for (int i = tid; i < 64 * 128; i += 256) {
        g_zb[rb * 128 + i] = __float2bfloat16(Z[rb * 128 + i]);
    }
}

// ---------------------------------------------------------------------------
// Flash kernel v2: 256 threads, intra-CTA split-K (warps 0-3: keys [0,32) of
// each 64-key tile; warps 4-7: keys [32,64)), ldmatrix fragments, cp.async
// double-buffered K/V tiles, smem merge of the two online-softmax partials.
// ---------------------------------------------------------------------------
extern __shared__ __align__(16) unsigned char dynsmem[];

__device__ __forceinline__ void load_tile_async(uint32_t sbase, int buf, int kt,
                                                int tid) {
    const __nv_bfloat16* Kg = g_t + kt * 64 * 128;
    const __nv_bfloat16* Vg = g_zb + kt * 64 * 128;
    uint32_t kB = sbase + buf * BUF_B;
#pragma unroll
    for (int j = 0; j < 8; j++) {
        int i = tid + j * 256;
        if (i < 1024) {
            int r = i >> 4, c = i & 15;
            cp_async16(kB + r * RSB + c * 16, Kg + r * 128 + c * 8);
        } else {
            int i2 = i - 1024;
            int r = i2 >> 4, c = i2 & 15;
            cp_async16(kB + TILE_B + r * RSB + c * 16, Vg + r * 128 + c * 8);
        }
    }
}

__global__ __launch_bounds__(256, 1) void flash_kernel(
    const float* __restrict__ Z, float* __restrict__ out)
{
    __nv_bfloat16* sm = (__nv_bfloat16*)dynsmem;
    const uint32_t sbase = smem_u32(sm);

    const int tid = threadIdx.x;
    const int lane = tid & 31;
    const int warp = tid >> 5;
    const int wg = warp >> 2;    // key-split group (0/1)
    const int w4 = warp & 3;     // row-block warp id
    const int g = lane >> 2;
    const int rb = blockIdx.x * 64;

    // ---- stage Q tile into buf0 K area, extract A-fragments via ldmatrix ----
#pragma unroll
    for (int j = 0; j < 4; j++) {
        int i = tid + j * 256;
        int r = i >> 4, c = i & 15;
        *(uint4*)&sm[r * RSH + c * 8] = *(const uint4*)&g_t[(rb + r) * 128 + c * 8];
    }
    __syncthreads();
    uint32_t qf[8][4];
    {
        int qrow = w4 * 16 + (lane & 7) + ((lane >> 3) & 1) * 8;
        int qcol = (lane >> 4) * 8;
#pragma unroll
        for (int kc = 0; kc < 8; kc++) {
            uint32_t a = sbase + qrow * RSB + (kc * 16 + qcol) * 2;
            ldm_x4(qf[kc][0], qf[kc][1], qf[kc][2], qf[kc][3], a);
        }
    }
    __syncthreads();

    // ---- prologue: async-load tile 0 into buffer 0 ----
    load_tile_async(sbase, 0, 0, tid);
    cp_commit();

    float o[16][4];
#pragma unroll
    for (int dn = 0; dn < 16; dn++) {
        o[dn][0] = 0.f; o[dn][1] = 0.f; o[dn][2] = 0.f; o[dn][3] = 0.f;
    }
    float m0 = -1e30f, m1 = -1e30f, l0 = 0.f, l1 = 0.f;

    // fragment-address components (constant across tiles)
    const int krow = wg * 32 + (lane & 7) + ((lane >= 16) ? 8 : 0);
    const int kcol = ((lane >> 3) & 1) * 8;
    const int vrow = wg * 32 + (lane & 15);
    const int vcol = (lane >> 4) * 8;

    for (int kt = 0; kt < NN / 64; kt++) {
        if (kt < NN / 64 - 1) {
            load_tile_async(sbase, (kt + 1) & 1, kt + 1, tid);
            cp_commit();
            cp_wait<1>();
        } else {
            cp_wait<0>();
        }
        __syncthreads();

        const uint32_t kB = sbase + (kt & 1) * BUF_B;
        const uint32_t vB = kB + TILE_B;

        // ---- S = Q K^T over this group's 32 keys ----
        float sc[4][4];
#pragma unroll
        for (int nc = 0; nc < 4; nc++) {
            sc[nc][0] = 0.f; sc[nc][1] = 0.f; sc[nc][2] = 0.f; sc[nc][3] = 0.f;
        }
#pragma unroll
        for (int nc16 = 0; nc16 < 2; nc16++) {
#pragma unroll
            for (int kc = 0; kc < 8; kc++) {
                uint32_t r0, r1, r2, r3;
                uint32_t a = kB + (krow + nc16 * 16) * RSB + (kc * 16 + kcol) * 2;
                ldm_x4(r0, r1, r2, r3, a);
                mma16816(sc[2 * nc16], qf[kc], r0, r1);
                mma16816(sc[2 * nc16 + 1], qf[kc], r2, r3);
            }
        }

        // ---- online softmax (per group) ----
        float mt0 = -1e30f, mt1 = -1e30f;
#pragma unroll
        for (int nc = 0; nc < 4; nc++) {
            mt0 = fmaxf(mt0, fmaxf(sc[nc][0], sc[nc][1]));
            mt1 = fmaxf(mt1, fmaxf(sc[nc][2], sc[nc][3]));
        }
        mt0 = fmaxf(mt0, __shfl_xor_sync(0xffffffffu, mt0, 1));
        mt0 = fmaxf(mt0, __shfl_xor_sync(0xffffffffu, mt0, 2));
        mt1 = fmaxf(mt1, __shfl_xor_sync(0xffffffffu, mt1, 1));
        mt1 = fmaxf(mt1, __shfl_xor_sync(0xffffffffu, mt1, 2));
        float mn0 = fmaxf(m0, mt0), mn1 = fmaxf(m1, mt1);
        float cs0 = __expf(m0 - mn0), cs1 = __expf(m1 - mn1);

        uint32_t pf[2][4];
        float s0 = 0.f, s1 = 0.f;
#pragma unroll
        for (int nc = 0; nc < 4; nc++) {
            float e0 = __expf(sc[nc][0] - mn0);
            float e1 = __expf(sc[nc][1] - mn0);
            float e2 = __expf(sc[nc][2] - mn1);
            float e3 = __expf(sc[nc][3] - mn1);
            s0 += e0 + e1; s1 += e2 + e3;
            if (nc & 1) { pf[nc >> 1][2] = packbf(e0, e1); pf[nc >> 1][3] = packbf(e2, e3); }
            else        { pf[nc >> 1][0] = packbf(e0, e1); pf[nc >> 1][1] = packbf(e2, e3); }
        }
        s0 += __shfl_xor_sync(0xffffffffu, s0, 1);
        s0 += __shfl_xor_sync(0xffffffffu, s0, 2);
        s1 += __shfl_xor_sync(0xffffffffu, s1, 1);
        s1 += __shfl_xor_sync(0xffffffffu, s1, 2);
        l0 = l0 * cs0 + s0;
        l1 = l1 * cs1 + s1;

#pragma unroll
        for (int dn = 0; dn < 16; dn++) {
            o[dn][0] *= cs0; o[dn][1] *= cs0; o[dn][2] *= cs1; o[dn][3] *= cs1;
        }

        // ---- O += P @ V via ldmatrix.trans on row-major V ----
#pragma unroll
        for (int dn16 = 0; dn16 < 8; dn16++) {
#pragma unroll
            for (int kc2 = 0; kc2 < 2; kc2++) {
                uint32_t r0, r1, r2, r3;
                uint32_t a = vB + (vrow + kc2 * 16) * RSB + (dn16 * 16 + vcol) * 2;
                ldm_x4_t(r0, r1, r2, r3, a);
                mma16816(o[2 * dn16], pf[kc2], r0, r1);
                mma16816(o[2 * dn16 + 1], pf[kc2], r2, r3);
            }
        }
        m0 = mn0; m1 = mn1;
        __syncthreads();
    }

    // ---- merge the two key-split partials (group 1 -> smem -> group 0) ----
    float* obuf = (float*)dynsmem;                      // [128][68]
    float* statb = (float*)(dynsmem + 128 * 68 * 4);    // [128][4]
    const int tt = tid & 127;
    if (wg == 1) {
#pragma unroll
        for (int dn = 0; dn < 16; dn++) {
            *(float4*)&obuf[tt * 68 + dn * 4] =
                make_float4(o[dn][0], o[dn][1], o[dn][2], o[dn][3]);
        }
        *(float4*)&statb[tt * 4] = make_float4(m0, m1, l0, l1);
    }
    __syncthreads();
    if (wg == 0) {
        float4 st = *(const float4*)&statb[tt * 4];
        float mn0 = fmaxf(m0, st.x), mn1 = fmaxf(m1, st.y);
        float a0 = __expf(m0 - mn0), p0 = __expf(st.x - mn0);
        float a1 = __expf(m1 - mn1), p1 = __expf(st.y - mn1);
        l0 = l0 * a0 + st.z * p0;
        l1 = l1 * a1 + st.w * p1;
        const float i0 = 1.f / l0, i1 = 1.f / l1;
        const int t4 = lane & 3;
        const int r0r = rb + w4 * 16 + g, r1r = r0r + 8;
#pragma unroll
        for (int dn = 0; dn < 16; dn++) {
            float4 po = *(const float4*)&obuf[tt * 68 + dn * 4];
            float v0 = o[dn][0] * a0 + po.x * p0;
            float v1 = o[dn][1] * a0 + po.y * p0;
            float v2 = o[dn][2] * a1 + po.z * p1;
            float v3 = o[dn][3] * a1 + po.w * p1;
            int c = dn * 8 + 2 * t4;
            float z00 = Z[r0r * 128 + c], z01 = Z[r0r * 128 + c + 1];
            float z10 = Z[r1r * 128 + c], z11 = Z[r1r * 128 + c + 1];
            out[r0r * 128 + c]     = z00 + TAU * (v0 * i0 - z00);
            out[r0r * 128 + c + 1] = z01 + TAU * (v1 * i0 - z01);
            out[r1r * 128 + c]     = z10 + TAU * (v2 * i1 - z10);
            out[r1r * 128 + c + 1] = z11 + TAU * (v3 * i1 - z11);
        }
    }
}

extern "C" void kernel_launch(void* const* d_in, const int* in_sizes, int n_in,
                              void* d_out, int out_size)
{
    (void)in_sizes; (void)n_in; (void)out_size;
    const float* Z  = (const float*)d_in[0];
    const float* W1 = (const float*)d_in[1];
    const float* b1 = (const float*)d_in[2];
    const float* W2 = (const float*)d_in[3];
    const float* b2 = (const float*)d_in[4];
    float* out = (float*)d_out;

    cudaFuncSetAttribute(flash_kernel,
                         cudaFuncAttributeMaxDynamicSharedMemorySize, SMEM_TOTAL);

    mlp_kernel<<<128, 256>>>(Z, W1, b1, W2, b2);
    flash_kernel<<<128, 256, SMEM_TOTAL>>>(Z, out);
}

// round 4
// speedup vs baseline: 3.0845x; 1.0988x over previous
#include <cuda_runtime.h>
#include <cuda_bf16.h>
#include <cstdint>

#define NN 8192
#define DD 128
#define TAU 0.1f
#define RSH 136                  // smem row stride in halves (128 data + 8 pad)
#define RSB 272                  // row stride in bytes
#define TILE_B 17408             // one K-or-V tile: 64*136*2 bytes
#define BUF_B 34816              // K+V tile pair
#define SMEM_TOTAL 69632         // 2 buffers
#define SQRT_LOG2E 1.2011224087864498f

static __device__ __nv_bfloat16 g_t[NN * DD];   // t' = MLP(Z)*sqrt(log2 e), bf16
static __device__ __nv_bfloat16 g_zb[NN * DD];  // Z in bf16 (V operand)
static __device__ float g_diag[NN];             // per-row diagonal logit (log2 units)

__device__ __forceinline__ uint32_t packbf(float a, float b) {
    __nv_bfloat162 h = __floats2bfloat162_rn(a, b);
    return *reinterpret_cast<uint32_t*>(&h);
}

__device__ __forceinline__ float ex2(float x) {
    float y;
    asm("ex2.approx.ftz.f32 %0, %1;" : "=f"(y) : "f"(x));
    return y;
}

__device__ __forceinline__ uint32_t smem_u32(const void* p) {
    return (uint32_t)__cvta_generic_to_shared(p);
}

__device__ __forceinline__ void mma16816(float c[4], const uint32_t a[4],
                                         uint32_t b0, uint32_t b1) {
    asm volatile(
        "mma.sync.aligned.m16n8k16.row.col.f32.bf16.bf16.f32 "
        "{%0,%1,%2,%3}, {%4,%5,%6,%7}, {%8,%9}, {%0,%1,%2,%3};\n"
        : "+f"(c[0]), "+f"(c[1]), "+f"(c[2]), "+f"(c[3])
        : "r"(a[0]), "r"(a[1]), "r"(a[2]), "r"(a[3]), "r"(b0), "r"(b1));
}

__device__ __forceinline__ void ldm_x4(uint32_t& r0, uint32_t& r1,
                                       uint32_t& r2, uint32_t& r3, uint32_t a) {
    asm volatile("ldmatrix.sync.aligned.m8n8.x4.shared.b16 {%0,%1,%2,%3}, [%4];\n"
                 : "=r"(r0), "=r"(r1), "=r"(r2), "=r"(r3) : "r"(a));
}
__device__ __forceinline__ void ldm_x4_t(uint32_t& r0, uint32_t& r1,
                                         uint32_t& r2, uint32_t& r3, uint32_t a) {
    asm volatile("ldmatrix.sync.aligned.m8n8.x4.trans.shared.b16 {%0,%1,%2,%3}, [%4];\n"
                 : "=r"(r0), "=r"(r1), "=r"(r2), "=r"(r3) : "r"(a));
}

__device__ __forceinline__ void cp_async16(uint32_t s, const void* g) {
    asm volatile("cp.async.cg.shared.global [%0], [%1], 16;\n" :: "r"(s), "l"(g));
}
__device__ __forceinline__ void cp_commit() {
    asm volatile("cp.async.commit_group;\n");
}
template <int N> __device__ __forceinline__ void cp_wait() {
    asm volatile("cp.async.wait_group %0;\n" :: "n"(N));
}

// ---------------------------------------------------------------------------
// MLP: t' = (relu(Z@W1+b1)@W2+b2) * sqrt(log2 e) -> bf16. Also Zb = bf16(Z)
// and g_diag[row] = sum(bf16(t')^2)  (the diagonal logit in log2 units,
// computed from the SAME bf16-rounded values the S-mma will consume).
// ---------------------------------------------------------------------------
__global__ __launch_bounds__(256) void mlp_kernel(
    const float* __restrict__ Z, const float* __restrict__ W1,
    const float* __restrict__ b1, const float* __restrict__ W2,
    const float* __restrict__ b2)
{
    __shared__ float wsT[128][36];
    __shared__ float zs[64][36];
    __shared__ __nv_bfloat16 hs[64][128];

    const int tid = threadIdx.x;
    const int j = tid & 127;
    const int rh = tid >> 7;
    const int rb = blockIdx.x * 64;

    float acc[32];
#pragma unroll
    for (int r = 0; r < 32; r++) acc[r] = 0.f;

    for (int kt = 0; kt < 4; kt++) {
        for (int i = tid; i < 4096; i += 256) {
            int kk = i >> 7, jj = i & 127;
            wsT[jj][kk] = W1[(kt * 32 + kk) * 128 + jj];
        }
        for (int i = tid; i < 2048; i += 256) {
            int r = i >> 5, kk = i & 31;
            zs[r][kk] = Z[(rb + r) * 128 + kt * 32 + kk];
        }
        __syncthreads();
#pragma unroll
        for (int kk4 = 0; kk4 < 8; kk4++) {
            float4 w = *(const float4*)&wsT[j][kk4 * 4];
#pragma unroll
            for (int r = 0; r < 32; r++) {
                float4 z = *(const float4*)&zs[rh * 32 + r][kk4 * 4];
                acc[r] += z.x * w.x + z.y * w.y + z.z * w.z + z.w * w.w;
            }
        }
        __syncthreads();
    }
    {
        float bb = b1[j];
#pragma unroll
        for (int r = 0; r < 32; r++) {
            float h = acc[r] + bb;
            hs[rh * 32 + r][j] = __float2bfloat16(h > 0.f ? h : 0.f);
            acc[r] = 0.f;
        }
    }
    __syncthreads();

    for (int kt = 0; kt < 4; kt++) {
        for (int i = tid; i < 4096; i += 256) {
            int kk = i >> 7, jj = i & 127;
            wsT[jj][kk] = W2[(kt * 32 + kk) * 128 + jj];
        }
        __syncthreads();
#pragma unroll
        for (int kk4 = 0; kk4 < 8; kk4++) {
            float4 w = *(const float4*)&wsT[j][kk4 * 4];
#pragma unroll
            for (int r = 0; r < 32; r++) {
                const uint32_t* hp =
                    (const uint32_t*)&hs[rh * 32 + r][kt * 32 + kk4 * 4];
                __nv_bfloat162 h01 = *(const __nv_bfloat162*)&hp[0];
                __nv_bfloat162 h23 = *(const __nv_bfloat162*)&hp[1];
                acc[r] += __bfloat162float(h01.x) * w.x +
                          __bfloat162float(h01.y) * w.y +
                          __bfloat162float(h23.x) * w.z +
                          __bfloat162float(h23.y) * w.w;
            }
        }
        __syncthreads();
    }
    __syncthreads();   // hs free for reuse as t' staging
    {
        float bb = b2[j];
#pragma unroll
        for (int r = 0; r < 32; r++) {
            int row = rb + rh * 32 + r;
            __nv_bfloat16 tp = __float2bfloat16((acc[r] + bb) * SQRT_LOG2E);
            g_t[row * 128 + j] = tp;
            hs[rh * 32 + r][j] = tp;
        }
    }
    for (int i = tid; i < 64 * 128; i += 256) {
        g_zb[rb * 128 + i] = __float2bfloat16(Z[rb * 128 + i]);
    }
    __syncthreads();
    if (tid < 64) {
        float s = 0.f;
#pragma unroll
        for (int k = 0; k < 128; k++) {
            float v = __bfloat162float(hs[tid][k]);
            s += v * v;
        }
        g_diag[rb + tid] = s;
    }
}

// ---------------------------------------------------------------------------
// Flash kernel v3: fixed per-row shift M = diagonal logit (no online max, no
// O-rescale, no per-tile reductions). p = exp2(s - M) directly; l summed
// per-lane and reduced once after the loop. 2-way key split + cp.async
// double buffering as before.
// ---------------------------------------------------------------------------
extern __shared__ __align__(16) unsigned char dynsmem[];

__device__ __forceinline__ void load_tile_async(uint32_t sbase, int buf, int kt,
                                                int tid) {
    const __nv_bfloat16* Kg = g_t + kt * 64 * 128;
    const __nv_bfloat16* Vg = g_zb + kt * 64 * 128;
    uint32_t kB = sbase + buf * BUF_B;
#pragma unroll
    for (int j = 0; j < 8; j++) {
        int i = tid + j * 256;
        if (i < 1024) {
            int r = i >> 4, c = i & 15;
            cp_async16(kB + r * RSB + c * 16, Kg + r * 128 + c * 8);
        } else {
            int i2 = i - 1024;
            int r = i2 >> 4, c = i2 & 15;
            cp_async16(kB + TILE_B + r * RSB + c * 16, Vg + r * 128 + c * 8);
        }
    }
}

__global__ __launch_bounds__(256, 1) void flash_kernel(
    const float* __restrict__ Z, float* __restrict__ out)
{
    __nv_bfloat16* sm = (__nv_bfloat16*)dynsmem;
    const uint32_t sbase = smem_u32(sm);

    const int tid = threadIdx.x;
    const int lane = tid & 31;
    const int warp = tid >> 5;
    const int wg = warp >> 2;    // key-split group (0/1)
    const int w4 = warp & 3;     // row-block warp id
    const int g = lane >> 2;
    const int rb = blockIdx.x * 64;

    // ---- stage Q tile into buf0 K area, extract A-fragments via ldmatrix ----
#pragma unroll
    for (int j = 0; j < 4; j++) {
        int i = tid + j * 256;
        int r = i >> 4, c = i & 15;
        *(uint4*)&sm[r * RSH + c * 8] = *(const uint4*)&g_t[(rb + r) * 128 + c * 8];
    }
    __syncthreads();
    uint32_t qf[8][4];
    {
        int qrow = w4 * 16 + (lane & 7) + ((lane >> 3) & 1) * 8;
        int qcol = (lane >> 4) * 8;
#pragma unroll
        for (int kc = 0; kc < 8; kc++) {
            uint32_t a = sbase + qrow * RSB + (kc * 16 + qcol) * 2;
            ldm_x4(qf[kc][0], qf[kc][1], qf[kc][2], qf[kc][3], a);
        }
    }
    __syncthreads();

    // per-row fixed softmax shift (diagonal logit, log2 units)
    const int r0q = rb + w4 * 16 + g;
    const float M0 = g_diag[r0q];
    const float M1 = g_diag[r0q + 8];

    // ---- prologue: async-load tile 0 into buffer 0 ----
    load_tile_async(sbase, 0, 0, tid);
    cp_commit();

    float o[16][4];
#pragma unroll
    for (int dn = 0; dn < 16; dn++) {
        o[dn][0] = 0.f; o[dn][1] = 0.f; o[dn][2] = 0.f; o[dn][3] = 0.f;
    }
    float l0 = 0.f, l1 = 0.f;

    const int krow = wg * 32 + (lane & 7) + ((lane >= 16) ? 8 : 0);
    const int kcol = ((lane >> 3) & 1) * 8;
    const int vrow = wg * 32 + (lane & 15);
    const int vcol = (lane >> 4) * 8;

    for (int kt = 0; kt < NN / 64; kt++) {
        if (kt < NN / 64 - 1) {
            load_tile_async(sbase, (kt + 1) & 1, kt + 1, tid);
            cp_commit();
            cp_wait<1>();
        } else {
            cp_wait<0>();
        }
        __syncthreads();

        const uint32_t kB = sbase + (kt & 1) * BUF_B;
        const uint32_t vB = kB + TILE_B;

        // ---- S = Q K^T over this group's 32 keys ----
        float sc[4][4];
#pragma unroll
        for (int nc = 0; nc < 4; nc++) {
            sc[nc][0] = 0.f; sc[nc][1] = 0.f; sc[nc][2] = 0.f; sc[nc][3] = 0.f;
        }
#pragma unroll
        for (int nc16 = 0; nc16 < 2; nc16++) {
#pragma unroll
            for (int kc = 0; kc < 8; kc++) {
                uint32_t r0, r1, r2, r3;
                uint32_t a = kB + (krow + nc16 * 16) * RSB + (kc * 16 + kcol) * 2;
                ldm_x4(r0, r1, r2, r3, a);
                mma16816(sc[2 * nc16], qf[kc], r0, r1);
                mma16816(sc[2 * nc16 + 1], qf[kc], r2, r3);
            }
        }

        // ---- p = exp2(s - M), accumulate l ----
        uint32_t pf[2][4];
#pragma unroll
        for (int nc = 0; nc < 4; nc++) {
            float e0 = ex2(sc[nc][0] - M0);
            float e1 = ex2(sc[nc][1] - M0);
            float e2 = ex2(sc[nc][2] - M1);
            float e3 = ex2(sc[nc][3] - M1);
            l0 += e0 + e1; l1 += e2 + e3;
            if (nc & 1) { pf[nc >> 1][2] = packbf(e0, e1); pf[nc >> 1][3] = packbf(e2, e3); }
            else        { pf[nc >> 1][0] = packbf(e0, e1); pf[nc >> 1][1] = packbf(e2, e3); }
        }

        // ---- O += P @ V via ldmatrix.trans on row-major V ----
#pragma unroll
        for (int dn16 = 0; dn16 < 8; dn16++) {
#pragma unroll
            for (int kc2 = 0; kc2 < 2; kc2++) {
                uint32_t r0, r1, r2, r3;
                uint32_t a = vB + (vrow + kc2 * 16) * RSB + (dn16 * 16 + vcol) * 2;
                ldm_x4_t(r0, r1, r2, r3, a);
                mma16816(o[2 * dn16], pf[kc2], r0, r1);
                mma16816(o[2 * dn16 + 1], pf[kc2], r2, r3);
            }
        }
        __syncthreads();
    }

    // one-time l reduction across the quad (lanes sharing a row)
    l0 += __shfl_xor_sync(0xffffffffu, l0, 1);
    l0 += __shfl_xor_sync(0xffffffffu, l0, 2);
    l1 += __shfl_xor_sync(0xffffffffu, l1, 1);
    l1 += __shfl_xor_sync(0xffffffffu, l1, 2);

    // ---- merge the two key-split partials (plain adds — same shift M) ----
    float* obuf = (float*)dynsmem;                      // [128][68]
    float* statb = (float*)(dynsmem + 128 * 68 * 4);    // [128][2]
    const int tt = tid & 127;
    if (wg == 1) {
#pragma unroll
        for (int dn = 0; dn < 16; dn++) {
            *(float4*)&obuf[tt * 68 + dn * 4] =
                make_float4(o[dn][0], o[dn][1], o[dn][2], o[dn][3]);
        }
        statb[tt * 2] = l0;
        statb[tt * 2 + 1] = l1;
    }
    __syncthreads();
    if (wg == 0) {
        l0 += statb[tt * 2];
        l1 += statb[tt * 2 + 1];
        const float i0 = 1.f / l0, i1 = 1.f / l1;
        const int t4 = lane & 3;
        const int r0r = rb + w4 * 16 + g, r1r = r0r + 8;
#pragma unroll
        for (int dn = 0; dn < 16; dn++) {
            float4 po = *(const float4*)&obuf[tt * 68 + dn * 4];
            float v0 = o[dn][0] + po.x;
            float v1 = o[dn][1] + po.y;
            float v2 = o[dn][2] + po.z;
            float v3 = o[dn][3] + po.w;
            int c = dn * 8 + 2 * t4;
            float z00 = Z[r0r * 128 + c], z01 = Z[r0r * 128 + c + 1];
            float z10 = Z[r1r * 128 + c], z11 = Z[r1r * 128 + c + 1];
            out[r0r * 128 + c]     = z00 + TAU * (v0 * i0 - z00);
            out[r0r * 128 + c + 1] = z01 + TAU * (v1 * i0 - z01);
            out[r1r * 128 + c]     = z10 + TAU * (v2 * i1 - z10);
            out[r1r * 128 + c + 1] = z11 + TAU * (v3 * i1 - z11);
        }
    }
}

extern "C" void kernel_launch(void* const* d_in, const int* in_sizes, int n_in,
                              void* d_out, int out_size)
{
    (void)in_sizes; (void)n_in; (void)out_size;
    const float* Z  = (const float*)d_in[0];
    const float* W1 = (const float*)d_in[1];
    const float* b1 = (const float*)d_in[2];
    const float* W2 = (const float*)d_in[3];
    const float* b2 = (const float*)d_in[4];
    float* out = (float*)d_out;

    cudaFuncSetAttribute(flash_kernel,
                         cudaFuncAttributeMaxDynamicSharedMemorySize, SMEM_TOTAL);

    mlp_kernel<<<128, 256>>>(Z, W1, b1, W2, b2);
    flash_kernel<<<128, 256, SMEM_TOTAL>>>(Z, out);
}

// round 8
// speedup vs baseline: 3.6236x; 1.1748x over previous
#include <cuda_runtime.h>
#include <cuda_bf16.h>
#include <cstdint>

#define NN 8192
#define DD 128
#define TAU 0.1f
#define RSH 136                  // smem row stride in halves (128 data + 8 pad)
#define RSB 272                  // row stride in bytes
#define TILE_B 17408             // one K-or-V tile: 64*136*2 bytes
#define BUF_B 34816              // K+V tile pair
#define SMEM_TOTAL 69632         // 2 buffers (also covers MLP layout)
#define SQRT_LOG2E 1.2011224087864498f

// MLP smem layout (bytes, within the same 69632 dynamic allocation)
#define MW_OFF 0                 // W tile: 128 x RSH bf16 = 34816
#define MA_OFF 34816             // A tile: 64 x RSH bf16 = 17408
#define MH_OFF 52224             // H tile: 64 x RSH bf16 = 17408

static __device__ __nv_bfloat16 g_t[NN * DD];   // t' = MLP(Z)*sqrt(log2 e), bf16
static __device__ __nv_bfloat16 g_zb[NN * DD];  // Z in bf16 (V operand)
static __device__ float g_diag[NN];             // per-row diagonal logit (log2 units)

__device__ __forceinline__ uint32_t packbf(float a, float b) {
    __nv_bfloat162 h = __floats2bfloat162_rn(a, b);
    return *reinterpret_cast<uint32_t*>(&h);
}

__device__ __forceinline__ float ex2(float x) {
    float y;
    asm("ex2.approx.ftz.f32 %0, %1;" : "=f"(y) : "f"(x));
    return y;
}

__device__ __forceinline__ uint32_t smem_u32(const void* p) {
    return (uint32_t)__cvta_generic_to_shared(p);
}

__device__ __forceinline__ void mma16816(float c[4], const uint32_t a[4],
                                         uint32_t b0, uint32_t b1) {
    asm volatile(
        "mma.sync.aligned.m16n8k16.row.col.f32.bf16.bf16.f32 "
        "{%0,%1,%2,%3}, {%4,%5,%6,%7}, {%8,%9}, {%0,%1,%2,%3};\n"
        : "+f"(c[0]), "+f"(c[1]), "+f"(c[2]), "+f"(c[3])
        : "r"(a[0]), "r"(a[1]), "r"(a[2]), "r"(a[3]), "r"(b0), "r"(b1));
}

__device__ __forceinline__ void ldm_x4(uint32_t& r0, uint32_t& r1,
                                       uint32_t& r2, uint32_t& r3, uint32_t a) {
    asm volatile("ldmatrix.sync.aligned.m8n8.x4.shared.b16 {%0,%1,%2,%3}, [%4];\n"
                 : "=r"(r0), "=r"(r1), "=r"(r2), "=r"(r3) : "r"(a));
}
__device__ __forceinline__ void ldm_x4_t(uint32_t& r0, uint32_t& r1,
                                         uint32_t& r2, uint32_t& r3, uint32_t a) {
    asm volatile("ldmatrix.sync.aligned.m8n8.x4.trans.shared.b16 {%0,%1,%2,%3}, [%4];\n"
                 : "=r"(r0), "=r"(r1), "=r"(r2), "=r"(r3) : "r"(a));
}

__device__ __forceinline__ void cp_async16(uint32_t s, const void* g) {
    asm volatile("cp.async.cg.shared.global [%0], [%1], 16;\n" :: "r"(s), "l"(g));
}
__device__ __forceinline__ void cp_commit() {
    asm volatile("cp.async.commit_group;\n");
}
template <int N> __device__ __forceinline__ void cp_wait() {
    asm volatile("cp.async.wait_group %0;\n" :: "n"(N));
}

extern __shared__ __align__(16) unsigned char dynsmem[];

// ---------------------------------------------------------------------------
// MLP v2 (tensor-core): t' = (relu(Zb@W1b+b1)@W2b+b2)*sqrt(log2 e) -> g_t.
// Also g_zb = bf16(Z), g_diag[row] = sum(bf16(t')^2).
// Grid 128 x 256 threads; 64 rows/CTA. W staged bf16 in smem; A-frags via
// ldmatrix (row-major), B-frags via ldmatrix.trans on W[k][n] rows — the
// exact fragment patterns already validated in the flash kernel.
// ---------------------------------------------------------------------------
__global__ __launch_bounds__(256) void mlp_kernel(
    const float* __restrict__ Z, const float* __restrict__ W1,
    const float* __restrict__ b1, const float* __restrict__ W2,
    const float* __restrict__ b2)
{
    __nv_bfloat16* sW = (__nv_bfloat16*)(dynsmem + MW_OFF);
    __nv_bfloat16* sA = (__nv_bfloat16*)(dynsmem + MA_OFF);
    __nv_bfloat16* sH = (__nv_bfloat16*)(dynsmem + MH_OFF);
    const uint32_t sWb = smem_u32(sW);
    const uint32_t sAb = smem_u32(sA);
    const uint32_t sHb = smem_u32(sH);

    const int tid = threadIdx.x;
    const int lane = tid & 31;
    const int warp = tid >> 5;
    const int mrow = (warp & 3) * 16;     // 16-row block within the 64-row tile
    const int nh = (warp >> 2) * 64;      // output-column half
    const int g = lane >> 2;
    const int t4 = lane & 3;
    const int rb = blockIdx.x * 64;

    // stage Zb (smem + g_zb) and W1 (bf16)
    for (int i = tid; i < 64 * 128; i += 256) {
        int r = i >> 7, c = i & 127;
        __nv_bfloat16 z = __float2bfloat16(Z[(rb + r) * 128 + c]);
        sA[r * RSH + c] = z;
        g_zb[rb * 128 + i] = z;
    }
    for (int i = tid; i < 128 * 128; i += 256) {
        int r = i >> 7, c = i & 127;
        sW[r * RSH + c] = __float2bfloat16(W1[i]);
    }
    __syncthreads();

    // fragment address components
    const int arow = mrow + (lane & 7) + ((lane >> 3) & 1) * 8;
    const int acol = (lane >> 4) * 8;
    const int brow = lane & 15;
    const int bcol = (lane >> 4) * 8;

    uint32_t af[8][4];
#pragma unroll
    for (int kc = 0; kc < 8; kc++)
        ldm_x4(af[kc][0], af[kc][1], af[kc][2], af[kc][3],
               sAb + arow * RSB + (kc * 16 + acol) * 2);

    // ---- layer 1: H = relu(Zb @ W1 + b1) ----
    float acc[8][4];
#pragma unroll
    for (int j = 0; j < 8; j++) {
        acc[j][0] = 0.f; acc[j][1] = 0.f; acc[j][2] = 0.f; acc[j][3] = 0.f;
    }
#pragma unroll
    for (int nc16 = 0; nc16 < 4; nc16++) {
#pragma unroll
        for (int kc = 0; kc < 8; kc++) {
            uint32_t r0, r1, r2, r3;
            ldm_x4_t(r0, r1, r2, r3,
                     sWb + (kc * 16 + brow) * RSB + (nh + nc16 * 16 + bcol) * 2);
            mma16816(acc[2 * nc16], af[kc], r0, r1);
            mma16816(acc[2 * nc16 + 1], af[kc], r2, r3);
        }
    }
#pragma unroll
    for (int j = 0; j < 8; j++) {
        int ncol = nh + (j >> 1) * 16 + (j & 1) * 8 + 2 * t4;
        float bb0 = b1[ncol], bb1 = b1[ncol + 1];
        float h0 = fmaxf(acc[j][0] + bb0, 0.f);
        float h1 = fmaxf(acc[j][1] + bb1, 0.f);
        float h2 = fmaxf(acc[j][2] + bb0, 0.f);
        float h3 = fmaxf(acc[j][3] + bb1, 0.f);
        *(uint32_t*)&sH[(mrow + g) * RSH + ncol] = packbf(h0, h1);
        *(uint32_t*)&sH[(mrow + g + 8) * RSH + ncol] = packbf(h2, h3);
    }
    __syncthreads();   // layer-1 reads of sW done; sH complete

    // stage W2; extract layer-2 A-frags from sH
    for (int i = tid; i < 128 * 128; i += 256) {
        int r = i >> 7, c = i & 127;
        sW[r * RSH + c] = __float2bfloat16(W2[i]);
    }
#pragma unroll
    for (int kc = 0; kc < 8; kc++)
        ldm_x4(af[kc][0], af[kc][1], af[kc][2], af[kc][3],
               sHb + arow * RSB + (kc * 16 + acol) * 2);
#pragma unroll
    for (int j = 0; j < 8; j++) {
        acc[j][0] = 0.f; acc[j][1] = 0.f; acc[j][2] = 0.f; acc[j][3] = 0.f;
    }
    __syncthreads();   // sW now holds W2 everywhere

    // ---- layer 2: T = H @ W2 + b2, scaled, -> g_t and sA (for diag) ----
#pragma unroll
    for (int nc16 = 0; nc16 < 4; nc16++) {
#pragma unroll
        for (int kc = 0; kc < 8; kc++) {
            uint32_t r0, r1, r2, r3;
            ldm_x4_t(r0, r1, r2, r3,
                     sWb + (kc * 16 + brow) * RSB + (nh + nc16 * 16 + bcol) * 2);
            mma16816(acc[2 * nc16], af[kc], r0, r1);
            mma16816(acc[2 * nc16 + 1], af[kc], r2, r3);
        }
    }
#pragma unroll
    for (int j = 0; j < 8; j++) {
        int ncol = nh + (j >> 1) * 16 + (j & 1) * 8 + 2 * t4;
        float bb0 = b2[ncol], bb1 = b2[ncol + 1];
        uint32_t p0 = packbf((acc[j][0] + bb0) * SQRT_LOG2E,
                             (acc[j][1] + bb1) * SQRT_LOG2E);
        uint32_t p1 = packbf((acc[j][2] + bb0) * SQRT_LOG2E,
                             (acc[j][3] + bb1) * SQRT_LOG2E);
        int r0r = mrow + g, r1r = mrow + g + 8;
        *(uint32_t*)&sA[r0r * RSH + ncol] = p0;
        *(uint32_t*)&sA[r1r * RSH + ncol] = p1;
        *(uint32_t*)&g_t[(rb + r0r) * 128 + ncol] = p0;
        *(uint32_t*)&g_t[(rb + r1r) * 128 + ncol] = p1;
    }
    __syncthreads();

    // diagonal logit from the SAME bf16 values the S-mma will consume
    if (tid < 64) {
        float s = 0.f;
#pragma unroll
        for (int k = 0; k < 128; k++) {
            float v = __bfloat162float(sA[tid * RSH + k]);
            s += v * v;
        }
        g_diag[rb + tid] = s;
    }
}

// ---------------------------------------------------------------------------
// Flash kernel (unchanged from the 140us R4 version): fixed per-row shift
// M = diagonal logit; p = exp2(s - M); 2-way key split; cp.async double
// buffering; merge by plain adds.
// ---------------------------------------------------------------------------
__device__ __forceinline__ void load_tile_async(uint32_t sbase, int buf, int kt,
                                                int tid) {
    const __nv_bfloat16* Kg = g_t + kt * 64 * 128;
    const __nv_bfloat16* Vg = g_zb + kt * 64 * 128;
    uint32_t kB = sbase + buf * BUF_B;
#pragma unroll
    for (int j = 0; j < 8; j++) {
        int i = tid + j * 256;
        if (i < 1024) {
            int r = i >> 4, c = i & 15;
            cp_async16(kB + r * RSB + c * 16, Kg + r * 128 + c * 8);
        } else {
            int i2 = i - 1024;
            int r = i2 >> 4, c = i2 & 15;
            cp_async16(kB + TILE_B + r * RSB + c * 16, Vg + r * 128 + c * 8);
        }
    }
}

__global__ __launch_bounds__(256, 1) void flash_kernel(
    const float* __restrict__ Z, float* __restrict__ out)
{
    __nv_bfloat16* sm = (__nv_bfloat16*)dynsmem;
    const uint32_t sbase = smem_u32(sm);

    const int tid = threadIdx.x;
    const int lane = tid & 31;
    const int warp = tid >> 5;
    const int wg = warp >> 2;    // key-split group (0/1)
    const int w4 = warp & 3;     // row-block warp id
    const int g = lane >> 2;
    const int rb = blockIdx.x * 64;

    // ---- stage Q tile into buf0 K area, extract A-fragments via ldmatrix ----
#pragma unroll
    for (int j = 0; j < 4; j++) {
        int i = tid + j * 256;
        int r = i >> 4, c = i & 15;
        *(uint4*)&sm[r * RSH + c * 8] = *(const uint4*)&g_t[(rb + r) * 128 + c * 8];
    }
    __syncthreads();
    uint32_t qf[8][4];
    {
        int qrow = w4 * 16 + (lane & 7) + ((lane >> 3) & 1) * 8;
        int qcol = (lane >> 4) * 8;
#pragma unroll
        for (int kc = 0; kc < 8; kc++) {
            uint32_t a = sbase + qrow * RSB + (kc * 16 + qcol) * 2;
            ldm_x4(qf[kc][0], qf[kc][1], qf[kc][2], qf[kc][3], a);
        }
    }
    __syncthreads();

    // per-row fixed softmax shift (diagonal logit, log2 units)
    const int r0q = rb + w4 * 16 + g;
    const float M0 = g_diag[r0q];
    const float M1 = g_diag[r0q + 8];

    // ---- prologue: async-load tile 0 into buffer 0 ----
    load_tile_async(sbase, 0, 0, tid);
    cp_commit();

    float o[16][4];
#pragma unroll
    for (int dn = 0; dn < 16; dn++) {
        o[dn][0] = 0.f; o[dn][1] = 0.f; o[dn][2] = 0.f; o[dn][3] = 0.f;
    }
    float l0 = 0.f, l1 = 0.f;

    const int krow = wg * 32 + (lane & 7) + ((lane >= 16) ? 8 : 0);
    const int kcol = ((lane >> 3) & 1) * 8;
    const int vrow = wg * 32 + (lane & 15);
    const int vcol = (lane >> 4) * 8;

    for (int kt = 0; kt < NN / 64; kt++) {
        if (kt < NN / 64 - 1) {
            load_tile_async(sbase, (kt + 1) & 1, kt + 1, tid);
            cp_commit();
            cp_wait<1>();
        } else {
            cp_wait<0>();
        }
        __syncthreads();

        const uint32_t kB = sbase + (kt & 1) * BUF_B;
        const uint32_t vB = kB + TILE_B;

        // ---- S = Q K^T over this group's 32 keys ----
        float sc[4][4];
#pragma unroll
        for (int nc = 0; nc < 4; nc++) {
            sc[nc][0] = 0.f; sc[nc][1] = 0.f; sc[nc][2] = 0.f; sc[nc][3] = 0.f;
        }
#pragma unroll
        for (int nc16 = 0; nc16 < 2; nc16++) {
#pragma unroll
            for (int kc = 0; kc < 8; kc++) {
                uint32_t r0, r1, r2, r3;
                uint32_t a = kB + (krow + nc16 * 16) * RSB + (kc * 16 + kcol) * 2;
                ldm_x4(r0, r1, r2, r3, a);
                mma16816(sc[2 * nc16], qf[kc], r0, r1);
                mma16816(sc[2 * nc16 + 1], qf[kc], r2, r3);
            }
        }

        // ---- p = exp2(s - M), accumulate l ----
        uint32_t pf[2][4];
#pragma unroll
        for (int nc = 0; nc < 4; nc++) {
            float e0 = ex2(sc[nc][0] - M0);
            float e1 = ex2(sc[nc][1] - M0);
            float e2 = ex2(sc[nc][2] - M1);
            float e3 = ex2(sc[nc][3] - M1);
            l0 += e0 + e1; l1 += e2 + e3;
            if (nc & 1) { pf[nc >> 1][2] = packbf(e0, e1); pf[nc >> 1][3] = packbf(e2, e3); }
            else        { pf[nc >> 1][0] = packbf(e0, e1); pf[nc >> 1][1] = packbf(e2, e3); }
        }

        // ---- O += P @ V via ldmatrix.trans on row-major V ----
#pragma unroll
        for (int dn16 = 0; dn16 < 8; dn16++) {
#pragma unroll
            for (int kc2 = 0; kc2 < 2; kc2++) {
                uint32_t r0, r1, r2, r3;
                uint32_t a = vB + (vrow + kc2 * 16) * RSB + (dn16 * 16 + vcol) * 2;
                ldm_x4_t(r0, r1, r2, r3, a);
                mma16816(o[2 * dn16], pf[kc2], r0, r1);
                mma16816(o[2 * dn16 + 1], pf[kc2], r2, r3);
            }
        }
        __syncthreads();
    }

    // one-time l reduction across the quad (lanes sharing a row)
    l0 += __shfl_xor_sync(0xffffffffu, l0, 1);
    l0 += __shfl_xor_sync(0xffffffffu, l0, 2);
    l1 += __shfl_xor_sync(0xffffffffu, l1, 1);
    l1 += __shfl_xor_sync(0xffffffffu, l1, 2);

    // ---- merge the two key-split partials (plain adds — same shift M) ----
    float* obuf = (float*)dynsmem;                      // [128][68]
    float* statb = (float*)(dynsmem + 128 * 68 * 4);    // [128][2]
    const int tt = tid & 127;
    if (wg == 1) {
#pragma unroll
        for (int dn = 0; dn < 16; dn++) {
            *(float4*)&obuf[tt * 68 + dn * 4] =
                make_float4(o[dn][0], o[dn][1], o[dn][2], o[dn][3]);
        }
        statb[tt * 2] = l0;
        statb[tt * 2 + 1] = l1;
    }
    __syncthreads();
    if (wg == 0) {
        l0 += statb[tt * 2];
        l1 += statb[tt * 2 + 1];
        const float i0 = 1.f / l0, i1 = 1.f / l1;
        const int t4 = lane & 3;
        const int r0r = rb + w4 * 16 + g, r1r = r0r + 8;
#pragma unroll
        for (int dn = 0; dn < 16; dn++) {
            float4 po = *(const float4*)&obuf[tt * 68 + dn * 4];
            float v0 = o[dn][0] + po.x;
            float v1 = o[dn][1] + po.y;
            float v2 = o[dn][2] + po.z;
            float v3 = o[dn][3] + po.w;
            int c = dn * 8 + 2 * t4;
            float z00 = Z[r0r * 128 + c], z01 = Z[r0r * 128 + c + 1];
            float z10 = Z[r1r * 128 + c], z11 = Z[r1r * 128 + c + 1];
            out[r0r * 128 + c]     = z00 + TAU * (v0 * i0 - z00);
            out[r0r * 128 + c + 1] = z01 + TAU * (v1 * i0 - z01);
            out[r1r * 128 + c]     = z10 + TAU * (v2 * i1 - z10);
            out[r1r * 128 + c + 1] = z11 + TAU * (v3 * i1 - z11);
        }
    }
}

extern "C" void kernel_launch(void* const* d_in, const int* in_sizes, int n_in,
                              void* d_out, int out_size)
{
    (void)in_sizes; (void)n_in; (void)out_size;
    const float* Z  = (const float*)d_in[0];
    const float* W1 = (const float*)d_in[1];
    const float* b1 = (const float*)d_in[2];
    const float* W2 = (const float*)d_in[3];
    const float* b2 = (const float*)d_in[4];
    float* out = (float*)d_out;

    cudaFuncSetAttribute(mlp_kernel,
                         cudaFuncAttributeMaxDynamicSharedMemorySize, SMEM_TOTAL);
    cudaFuncSetAttribute(flash_kernel,
                         cudaFuncAttributeMaxDynamicSharedMemorySize, SMEM_TOTAL);

    mlp_kernel<<<128, 256, SMEM_TOTAL>>>(Z, W1, b1, W2, b2);
    flash_kernel<<<128, 256, SMEM_TOTAL>>>(Z, out);
}